// round 4
// baseline (speedup 1.0000x reference)
#include <cuda_runtime.h>
#include <cuda_bf16.h>
#include <cstdint>

// LengthRegulator. Live work (predictor is dead code in the reference):
//   cum = cumsum(target_durations, axis=1)
//   padded[b,f,:] = (f < cum[b,-1]) ? x[b, upper_bound(cum[b], f), :] : 0
//   durations_out = target_durations
// B=8, T=1024, D=1024, F=8192. Output fp32: [B*F*D padded][B*T durations].
//
// R3: 4 tokens per expand block -> 4x MLP on the x-row loads, 32 independent
// stores queued per block, 3.4x fewer blocks.

#define LR_B 8
#define LR_T 1024
#define LR_D 1024
#define LR_F 8192
#define LR_V4 (LR_D / 4)          // 256 float4 per row
#define TPB   4                   // tokens per expand block
#define TBLK  (LR_T / TPB)        // 256 token blocks per batch
#define ZCHUNK 128
#define ZBLOCKS (LR_F / ZCHUNK)   // 64

__device__ int g_cum[LR_B * LR_T];   // inclusive cumsum of durations

// ---------------------------------------------------------------------------
// Kernel 1: per-batch inclusive scan (warp shuffles) + durations pass-through.
// ---------------------------------------------------------------------------
__global__ void lr_scan_kernel(const int* __restrict__ dur,
                               float* __restrict__ dur_out) {
    __shared__ int warp_sums[32];
    const int b    = blockIdx.x;
    const int t    = threadIdx.x;
    const int lane = t & 31;
    const int wid  = t >> 5;

    const int v = dur[b * LR_T + t];
    if (dur_out) dur_out[b * LR_T + t] = (float)v;

    int s = v;
    #pragma unroll
    for (int o = 1; o < 32; o <<= 1) {
        int u = __shfl_up_sync(0xFFFFFFFFu, s, o);
        if (lane >= o) s += u;
    }
    if (lane == 31) warp_sums[wid] = s;
    __syncthreads();

    if (wid == 0) {
        int ws = warp_sums[lane];
        #pragma unroll
        for (int o = 1; o < 32; o <<= 1) {
            int u = __shfl_up_sync(0xFFFFFFFFu, ws, o);
            if (lane >= o) ws += u;
        }
        warp_sums[lane] = ws;
    }
    __syncthreads();

    const int prefix = (wid > 0) ? warp_sums[wid - 1] : 0;
    g_cum[b * LR_T + t] = s + prefix;
}

// ---------------------------------------------------------------------------
// Kernel 2: fused expand + zero-fill.
//   blockIdx.x <  TBLK : 4-token block — load 4 x rows, store each dur[] times
//   blockIdx.x >= TBLK : zero block — fill invalid frames in a 128-frame chunk
// ---------------------------------------------------------------------------
__global__ void __launch_bounds__(LR_V4)
lr_expand_kernel(const float* __restrict__ x,
                 const int* __restrict__ dur,
                 float* __restrict__ out) {
    const int b = blockIdx.y;
    const int i = threadIdx.x;  // 0..255

    if (blockIdx.x < TBLK) {
        const int t0 = blockIdx.x * TPB;

        // Index loads first (independent, broadcast within warp).
        int d[TPB], end[TPB];
        #pragma unroll
        for (int j = 0; j < TPB; ++j) {
            d[j]   = __ldg(&dur[b * LR_T + t0 + j]);
            end[j] = __ldg(&g_cum[b * LR_T + t0 + j]);
        }

        // Independent x-row loads (MLP = TPB). Rows with d==0 skipped.
        const float4* xb = reinterpret_cast<const float4*>(x) +
                           ((size_t)b * LR_T + t0) * LR_V4 + i;
        float4 v[TPB];
        #pragma unroll
        for (int j = 0; j < TPB; ++j) {
            if (d[j] > 0) v[j] = __ldg(&xb[(size_t)j * LR_V4]);
        }

        // Up to TPB*8 independent stores.
        float4* ob = reinterpret_cast<float4*>(out) +
                     ((size_t)b * LR_F) * LR_V4 + i;
        #pragma unroll
        for (int j = 0; j < TPB; ++j) {
            const int start = end[j] - d[j];
            float4* o = ob + (size_t)start * LR_V4;
            #pragma unroll
            for (int k = 0; k < 8; ++k) {  // DMAX bound
                if (k < d[j]) o[(size_t)k * LR_V4] = v[j];
            }
        }
    } else {
        const int chunk = blockIdx.x - TBLK;
        const int total = g_cum[b * LR_T + (LR_T - 1)];
        const int f0 = chunk * ZCHUNK;
        const int f1 = f0 + ZCHUNK;
        int fs = (f0 > total) ? f0 : total;
        if (fs >= f1) return;
        const float4 z = make_float4(0.f, 0.f, 0.f, 0.f);
        float4* o = reinterpret_cast<float4*>(out) +
                    ((size_t)b * LR_F + fs) * LR_V4 + i;
        for (int f = fs; f < f1; ++f, o += LR_V4) *o = z;
    }
}

extern "C" void kernel_launch(void* const* d_in, const int* in_sizes, int n_in,
                              void* d_out, int out_size) {
    const float* x   = (const float*)d_in[0];  // [B, T, D] fp32
    const int*   dur = (const int*)  d_in[1];  // [B, T] int32
    float* out = (float*)d_out;

    const long long padded_elems = (long long)LR_B * LR_F * LR_D;
    float* dur_out =
        ((long long)out_size >= padded_elems + (long long)LR_B * LR_T)
            ? out + padded_elems : nullptr;

    lr_scan_kernel<<<LR_B, LR_T>>>(dur, dur_out);

    dim3 grid(TBLK + ZBLOCKS, LR_B);
    lr_expand_kernel<<<grid, LR_V4>>>(x, dur, out);
}

// round 5
// speedup vs baseline: 1.3828x; 1.3828x over previous
#include <cuda_runtime.h>
#include <cuda_bf16.h>
#include <cstdint>

// LengthRegulator. Live work (predictor is dead code in the reference):
//   cum = cumsum(target_durations, axis=1)
//   padded[b,f,:] = (f < cum[b,-1]) ? x[b, upper_bound(cum[b], f), :] : 0
//   durations_out = target_durations
// B=8, T=1024, D=1024, F=8192. Output fp32: [B*F*D padded][B*T durations].
//
// R5: fine-grained zero-fill (16 frames/block -> ~2300 active zero blocks
// instead of ~288, removing the tail imbalance on the ~150MB zero region)
// + streaming stores for the 256MB output.

#define LR_B 8
#define LR_T 1024
#define LR_D 1024
#define LR_F 8192
#define LR_V4 (LR_D / 4)          // 256 float4 per row
#define TPB   4                   // tokens per expand block
#define TBLK  (LR_T / TPB)        // 256 token blocks per batch
#define ZCHUNK 16                 // frames per zero-fill block (fine-grained)
#define ZBLOCKS (LR_F / ZCHUNK)   // 512 zero blocks per batch

__device__ int g_cum[LR_B * LR_T];   // inclusive cumsum of durations

// ---------------------------------------------------------------------------
// Kernel 1: per-batch inclusive scan (warp shuffles) + durations pass-through.
// ---------------------------------------------------------------------------
__global__ void lr_scan_kernel(const int* __restrict__ dur,
                               float* __restrict__ dur_out) {
    __shared__ int warp_sums[32];
    const int b    = blockIdx.x;
    const int t    = threadIdx.x;
    const int lane = t & 31;
    const int wid  = t >> 5;

    const int v = dur[b * LR_T + t];
    if (dur_out) dur_out[b * LR_T + t] = (float)v;

    int s = v;
    #pragma unroll
    for (int o = 1; o < 32; o <<= 1) {
        int u = __shfl_up_sync(0xFFFFFFFFu, s, o);
        if (lane >= o) s += u;
    }
    if (lane == 31) warp_sums[wid] = s;
    __syncthreads();

    if (wid == 0) {
        int ws = warp_sums[lane];
        #pragma unroll
        for (int o = 1; o < 32; o <<= 1) {
            int u = __shfl_up_sync(0xFFFFFFFFu, ws, o);
            if (lane >= o) ws += u;
        }
        warp_sums[lane] = ws;
    }
    __syncthreads();

    const int prefix = (wid > 0) ? warp_sums[wid - 1] : 0;
    g_cum[b * LR_T + t] = s + prefix;
}

// ---------------------------------------------------------------------------
// Kernel 2: fused expand + zero-fill.
//   blockIdx.x <  TBLK : 4-token block — load 4 x rows, store each dur[] times
//   blockIdx.x >= TBLK : zero block — fill invalid frames in a 16-frame chunk
// ---------------------------------------------------------------------------
__global__ void __launch_bounds__(LR_V4)
lr_expand_kernel(const float* __restrict__ x,
                 const int* __restrict__ dur,
                 float* __restrict__ out) {
    const int b = blockIdx.y;
    const int i = threadIdx.x;  // 0..255

    if (blockIdx.x < TBLK) {
        const int t0 = blockIdx.x * TPB;

        int d[TPB], end[TPB];
        #pragma unroll
        for (int j = 0; j < TPB; ++j) {
            d[j]   = __ldg(&dur[b * LR_T + t0 + j]);
            end[j] = __ldg(&g_cum[b * LR_T + t0 + j]);
        }

        const float4* xb = reinterpret_cast<const float4*>(x) +
                           ((size_t)b * LR_T + t0) * LR_V4 + i;
        float4 v[TPB];
        #pragma unroll
        for (int j = 0; j < TPB; ++j) {
            if (d[j] > 0) v[j] = __ldg(&xb[(size_t)j * LR_V4]);
        }

        float4* ob = reinterpret_cast<float4*>(out) +
                     ((size_t)b * LR_F) * LR_V4 + i;
        #pragma unroll
        for (int j = 0; j < TPB; ++j) {
            const int start = end[j] - d[j];
            float4* o = ob + (size_t)start * LR_V4;
            #pragma unroll
            for (int k = 0; k < 8; ++k) {  // DMAX bound
                if (k < d[j]) __stcs(&o[(size_t)k * LR_V4], v[j]);
            }
        }
    } else {
        const int chunk = blockIdx.x - TBLK;
        const int total = g_cum[b * LR_T + (LR_T - 1)];
        const int f0 = chunk * ZCHUNK;
        const int f1 = f0 + ZCHUNK;
        int fs = (f0 > total) ? f0 : total;
        if (fs >= f1) return;
        const float4 z = make_float4(0.f, 0.f, 0.f, 0.f);
        float4* o = reinterpret_cast<float4*>(out) +
                    ((size_t)b * LR_F + fs) * LR_V4 + i;
        #pragma unroll 4
        for (int f = fs; f < f1; ++f, o += LR_V4) __stcs(o, z);
    }
}

extern "C" void kernel_launch(void* const* d_in, const int* in_sizes, int n_in,
                              void* d_out, int out_size) {
    const float* x   = (const float*)d_in[0];  // [B, T, D] fp32
    const int*   dur = (const int*)  d_in[1];  // [B, T] int32
    float* out = (float*)d_out;

    const long long padded_elems = (long long)LR_B * LR_F * LR_D;
    float* dur_out =
        ((long long)out_size >= padded_elems + (long long)LR_B * LR_T)
            ? out + padded_elems : nullptr;

    lr_scan_kernel<<<LR_B, LR_T>>>(dur, dur_out);

    dim3 grid(TBLK + ZBLOCKS, LR_B);
    lr_expand_kernel<<<grid, LR_V4>>>(x, dur, out);
}